// round 1
// baseline (speedup 1.0000x reference)
#include <cuda_runtime.h>

#define NUM_BINS  512
#define NUM_NODES 128
#define N_PAIRS   1024
#define K_ELEMS   16384

// Scratch (allocation-free rule: __device__ globals)
__device__ float g_hist[NUM_NODES * NUM_BINS];
__device__ float g_tw[NUM_NODES];
__device__ float g_cdf[NUM_NODES * NUM_BINS];

// ---------------------------------------------------------------------------
// Kernel 0: zero the accumulators (graph replays must be deterministic)
// ---------------------------------------------------------------------------
__global__ void zero_kernel() {
    int i = blockIdx.x * blockDim.x + threadIdx.x;
    if (i < NUM_NODES * NUM_BINS) g_hist[i] = 0.0f;
    if (i < NUM_NODES)            g_tw[i]   = 0.0f;
}

// ---------------------------------------------------------------------------
// Kernel 1: per-pair shared-memory histogram + total-weight accumulation.
// One block per pair. The contribution of a pair to hist[src] and hist[dst]
// is identical, so build ONE smem histogram and flush it to both rows.
// ---------------------------------------------------------------------------
__global__ __launch_bounds__(512) void hist_kernel(
    const float* __restrict__ res, const float* __restrict__ wgt,
    const int* __restrict__ src, const int* __restrict__ dst)
{
    __shared__ float sh_hist[NUM_BINS];
    __shared__ float sh_wsum;

    const int p   = blockIdx.x;
    const int tid = threadIdx.x;

    for (int i = tid; i < NUM_BINS; i += 512) sh_hist[i] = 0.0f;
    if (tid == 0) sh_wsum = 0.0f;
    __syncthreads();

    const float4* r4 = (const float4*)(res + (size_t)p * K_ELEMS);
    const float4* w4 = (const float4*)(wgt + (size_t)p * K_ELEMS);

    float wsum = 0.0f;
    const int n4 = K_ELEMS / 4;
    for (int i = tid; i < n4; i += 512) {
        float4 rv = r4[i];
        float4 wv = w4[i];
        float rr[4] = {rv.x, rv.y, rv.z, rv.w};
        float ww[4] = {wv.x, wv.y, wv.z, wv.w};
        #pragma unroll
        for (int j = 0; j < 4; j++) {
            wsum += ww[j];
            int b = (int)floorf(rr[j] * 512.0f);   // *2^9 exact in fp32
            if (b >= 0 && b < NUM_BINS)
                atomicAdd(&sh_hist[b], ww[j]);
        }
    }

    // warp-reduce wsum, then one smem atomic per warp
    #pragma unroll
    for (int o = 16; o > 0; o >>= 1)
        wsum += __shfl_down_sync(0xffffffffu, wsum, o);
    if ((tid & 31) == 0) atomicAdd(&sh_wsum, wsum);
    __syncthreads();

    const int s = src[p];
    const int d = dst[p];
    for (int i = tid; i < NUM_BINS; i += 512) {
        float h = sh_hist[i];
        atomicAdd(&g_hist[s * NUM_BINS + i], h);
        atomicAdd(&g_hist[d * NUM_BINS + i], h);
    }
    if (tid == 0) {
        atomicAdd(&g_tw[s], sh_wsum);
        atomicAdd(&g_tw[d], sh_wsum);
    }
}

// ---------------------------------------------------------------------------
// Kernel 2: cdf[node, :] = cumsum(hist[node, :] / (tw[node] + 1e-10))
// One block of 512 threads per node; block-wide inclusive scan.
// ---------------------------------------------------------------------------
__global__ __launch_bounds__(512) void cdf_kernel() {
    __shared__ float warp_sums[16];

    const int node = blockIdx.x;
    const int tid  = threadIdx.x;

    const float inv_tw = 1.0f / (g_tw[node] + 1e-10f);
    float x = g_hist[node * NUM_BINS + tid] * inv_tw;

    // intra-warp inclusive scan
    #pragma unroll
    for (int o = 1; o < 32; o <<= 1) {
        float y = __shfl_up_sync(0xffffffffu, x, o);
        if ((tid & 31) >= o) x += y;
    }
    if ((tid & 31) == 31) warp_sums[tid >> 5] = x;
    __syncthreads();

    if (tid < 16) {
        float s = warp_sums[tid];
        #pragma unroll
        for (int o = 1; o < 16; o <<= 1) {
            float y = __shfl_up_sync(0x0000ffffu, s, o);
            if (tid >= o) s += y;
        }
        warp_sums[tid] = s;
    }
    __syncthreads();

    float base = (tid >= 32) ? warp_sums[(tid >> 5) - 1] : 0.0f;
    g_cdf[node * NUM_BINS + tid] = x + base;
}

// ---------------------------------------------------------------------------
// Kernel 3: lookup. One block per pair; cdf rows for (src,dst) staged in smem.
// Output layout: out[0 : N*K) = src_cdf, out[N*K : 2*N*K) = dst_cdf.
// ---------------------------------------------------------------------------
__device__ __forceinline__ void lookup_one(float r, float w,
                                           const float* sh_s, const float* sh_d,
                                           float& os, float& od)
{
    int b = (int)floorf(r * 512.0f + 0.5f);
    bool valid = (b >= 0) && (b < NUM_BINS) && (w > 0.0f);
    int bc = min(max(b, 0), NUM_BINS - 1);
    os = valid ? sh_s[bc] : 2.0f;
    od = valid ? sh_d[bc] : 2.0f;
}

__global__ __launch_bounds__(512) void lookup_kernel(
    const float* __restrict__ res, const float* __restrict__ wgt,
    const int* __restrict__ src, const int* __restrict__ dst,
    float* __restrict__ out)
{
    __shared__ float sh_s[NUM_BINS];
    __shared__ float sh_d[NUM_BINS];

    const int p   = blockIdx.x;
    const int tid = threadIdx.x;
    const int s   = src[p];
    const int d   = dst[p];

    for (int i = tid; i < NUM_BINS; i += 512) {
        sh_s[i] = g_cdf[s * NUM_BINS + i];
        sh_d[i] = g_cdf[d * NUM_BINS + i];
    }
    __syncthreads();

    const float4* r4 = (const float4*)(res + (size_t)p * K_ELEMS);
    const float4* w4 = (const float4*)(wgt + (size_t)p * K_ELEMS);
    float4* o_s = (float4*)(out + (size_t)p * K_ELEMS);
    float4* o_d = (float4*)(out + (size_t)(N_PAIRS + p) * K_ELEMS);

    const int n4 = K_ELEMS / 4;
    for (int i = tid; i < n4; i += 512) {
        float4 rv = r4[i];
        float4 wv = w4[i];
        float4 os, od;
        lookup_one(rv.x, wv.x, sh_s, sh_d, os.x, od.x);
        lookup_one(rv.y, wv.y, sh_s, sh_d, os.y, od.y);
        lookup_one(rv.z, wv.z, sh_s, sh_d, os.z, od.z);
        lookup_one(rv.w, wv.w, sh_s, sh_d, os.w, od.w);
        o_s[i] = os;
        o_d[i] = od;
    }
}

// ---------------------------------------------------------------------------
extern "C" void kernel_launch(void* const* d_in, const int* in_sizes, int n_in,
                              void* d_out, int out_size)
{
    const float* res = (const float*)d_in[0];
    const float* wgt = (const float*)d_in[1];
    const int*   src = (const int*)d_in[2];
    const int*   dst = (const int*)d_in[3];
    float*       out = (float*)d_out;

    zero_kernel<<<(NUM_NODES * NUM_BINS + 255) / 256, 256>>>();
    hist_kernel<<<N_PAIRS, 512>>>(res, wgt, src, dst);
    cdf_kernel<<<NUM_NODES, 512>>>();
    lookup_kernel<<<N_PAIRS, 512>>>(res, wgt, src, dst, out);
}

// round 2
// speedup vs baseline: 1.0832x; 1.0832x over previous
#include <cuda_runtime.h>

#define NUM_BINS  512
#define NUM_NODES 128
#define N_PAIRS   1024
#define K_ELEMS   16384

// Scratch (allocation-free rule: __device__ globals, zero-initialized at load)
__device__ float g_hist[NUM_NODES * NUM_BINS];
__device__ float g_tw[NUM_NODES];
__device__ float g_cdf[NUM_NODES * NUM_BINS];
// 2-byte lookup code per element: bin index if valid, 0xFFFF sentinel if not.
__device__ unsigned short g_code[(size_t)N_PAIRS * K_ELEMS];

// ---------------------------------------------------------------------------
// Kernel 1: per-pair shared-memory histogram + total weight + lookup-code gen.
// One block per pair. Pair contributes identically to hist[src] and hist[dst],
// so one smem histogram, flushed twice.
// g_hist/g_tw are guaranteed zero on entry (zeroed by cdf_kernel after use).
// ---------------------------------------------------------------------------
__global__ __launch_bounds__(512) void hist_kernel(
    const float* __restrict__ res, const float* __restrict__ wgt,
    const int* __restrict__ src, const int* __restrict__ dst)
{
    __shared__ float sh_hist[NUM_BINS];
    __shared__ float sh_wsum;

    const int p   = blockIdx.x;
    const int tid = threadIdx.x;

    for (int i = tid; i < NUM_BINS; i += 512) sh_hist[i] = 0.0f;
    if (tid == 0) sh_wsum = 0.0f;
    __syncthreads();

    const float4* r4 = (const float4*)(res + (size_t)p * K_ELEMS);
    const float4* w4 = (const float4*)(wgt + (size_t)p * K_ELEMS);
    ushort4* c4 = (ushort4*)(g_code + (size_t)p * K_ELEMS);

    float wsum = 0.0f;
    const int n4 = K_ELEMS / 4;
    for (int i = tid; i < n4; i += 512) {
        float4 rv = r4[i];
        float4 wv = w4[i];
        float rr[4] = {rv.x, rv.y, rv.z, rv.w};
        float ww[4] = {wv.x, wv.y, wv.z, wv.w};
        unsigned short cc[4];
        #pragma unroll
        for (int j = 0; j < 4; j++) {
            wsum += ww[j];
            // histogram bin: floor(r*512)   (*2^9 is exact in fp32)
            int b = (int)floorf(rr[j] * 512.0f);
            if (b >= 0 && b < NUM_BINS)
                atomicAdd(&sh_hist[b], ww[j]);
            // lookup bin: floor(r*512 + 0.5), valid also requires w > 0
            int b2 = (int)floorf(rr[j] * 512.0f + 0.5f);
            bool valid = (b2 >= 0) && (b2 < NUM_BINS) && (ww[j] > 0.0f);
            cc[j] = valid ? (unsigned short)b2 : (unsigned short)0xFFFFu;
        }
        c4[i] = make_ushort4(cc[0], cc[1], cc[2], cc[3]);
    }

    // warp-reduce wsum, one smem atomic per warp
    #pragma unroll
    for (int o = 16; o > 0; o >>= 1)
        wsum += __shfl_down_sync(0xffffffffu, wsum, o);
    if ((tid & 31) == 0) atomicAdd(&sh_wsum, wsum);
    __syncthreads();

    const int s = src[p];
    const int d = dst[p];
    for (int i = tid; i < NUM_BINS; i += 512) {
        float h = sh_hist[i];
        atomicAdd(&g_hist[s * NUM_BINS + i], h);
        atomicAdd(&g_hist[d * NUM_BINS + i], h);
    }
    if (tid == 0) {
        atomicAdd(&g_tw[s], sh_wsum);
        atomicAdd(&g_tw[d], sh_wsum);
    }
}

// ---------------------------------------------------------------------------
// Kernel 2: cdf[node,:] = cumsum(hist[node,:] / (tw[node] + 1e-10)),
// then reset g_hist / g_tw to zero for the next invocation (keeps every
// graph replay deterministic without a separate zero kernel).
// ---------------------------------------------------------------------------
__global__ __launch_bounds__(512) void cdf_kernel() {
    __shared__ float warp_sums[16];

    const int node = blockIdx.x;
    const int tid  = threadIdx.x;

    const float inv_tw = 1.0f / (g_tw[node] + 1e-10f);
    float h = g_hist[node * NUM_BINS + tid];
    g_hist[node * NUM_BINS + tid] = 0.0f;     // reset for next call
    float x = h * inv_tw;

    // intra-warp inclusive scan
    #pragma unroll
    for (int o = 1; o < 32; o <<= 1) {
        float y = __shfl_up_sync(0xffffffffu, x, o);
        if ((tid & 31) >= o) x += y;
    }
    if ((tid & 31) == 31) warp_sums[tid >> 5] = x;
    __syncthreads();

    if (tid == 0) g_tw[node] = 0.0f;          // all reads of g_tw done pre-sync

    if (tid < 16) {
        float s = warp_sums[tid];
        #pragma unroll
        for (int o = 1; o < 16; o <<= 1) {
            float y = __shfl_up_sync(0x0000ffffu, s, o);
            if (tid >= o) s += y;
        }
        warp_sums[tid] = s;
    }
    __syncthreads();

    float base = (tid >= 32) ? warp_sums[(tid >> 5) - 1] : 0.0f;
    g_cdf[node * NUM_BINS + tid] = x + base;
}

// ---------------------------------------------------------------------------
// Kernel 3: lookup via cached 2-byte codes. One block per pair; the pair's
// two cdf rows staged in smem. Reads 2B/elem, writes 8B/elem.
// Output layout: out[0 : N*K) = src_cdf, out[N*K : 2*N*K) = dst_cdf.
// ---------------------------------------------------------------------------
__global__ __launch_bounds__(512) void lookup_kernel(
    const int* __restrict__ src, const int* __restrict__ dst,
    float* __restrict__ out)
{
    __shared__ float sh_s[NUM_BINS];
    __shared__ float sh_d[NUM_BINS];

    const int p   = blockIdx.x;
    const int tid = threadIdx.x;
    const int s   = src[p];
    const int d   = dst[p];

    for (int i = tid; i < NUM_BINS; i += 512) {
        sh_s[i] = g_cdf[s * NUM_BINS + i];
        sh_d[i] = g_cdf[d * NUM_BINS + i];
    }
    __syncthreads();

    const ushort4* c4 = (const ushort4*)(g_code + (size_t)p * K_ELEMS);
    float4* o_s = (float4*)(out + (size_t)p * K_ELEMS);
    float4* o_d = (float4*)(out + (size_t)(N_PAIRS + p) * K_ELEMS);

    const int n4 = K_ELEMS / 4;
    for (int i = tid; i < n4; i += 512) {
        ushort4 cv = c4[i];
        unsigned short cc[4] = {cv.x, cv.y, cv.z, cv.w};
        float4 os, od;
        float* pos = (float*)&os;
        float* pod = (float*)&od;
        #pragma unroll
        for (int j = 0; j < 4; j++) {
            unsigned short c = cc[j];
            if (c < NUM_BINS) {
                pos[j] = sh_s[c];
                pod[j] = sh_d[c];
            } else {
                pos[j] = 2.0f;
                pod[j] = 2.0f;
            }
        }
        o_s[i] = os;
        o_d[i] = od;
    }
}

// ---------------------------------------------------------------------------
extern "C" void kernel_launch(void* const* d_in, const int* in_sizes, int n_in,
                              void* d_out, int out_size)
{
    const float* res = (const float*)d_in[0];
    const float* wgt = (const float*)d_in[1];
    const int*   src = (const int*)d_in[2];
    const int*   dst = (const int*)d_in[3];
    float*       out = (float*)d_out;

    hist_kernel<<<N_PAIRS, 512>>>(res, wgt, src, dst);
    cdf_kernel<<<NUM_NODES, 512>>>();
    lookup_kernel<<<N_PAIRS, 512>>>(src, dst, out);
}

// round 3
// speedup vs baseline: 1.2993x; 1.1995x over previous
#include <cuda_runtime.h>

#define NUM_BINS  512
#define NUM_NODES 128
#define N_PAIRS   1024
#define K_ELEMS   16384
#define NREP      32   // one histogram copy per lane -> conflict-free ATOMS

// Scratch (allocation-free rule: __device__ globals, zero-initialized at load)
__device__ float g_hist[NUM_NODES * NUM_BINS];
__device__ float g_tw[NUM_NODES];
__device__ float g_cdf[NUM_NODES * NUM_BINS];
// 2-byte lookup code per element: bin index if valid, 0xFFFF sentinel if not.
__device__ unsigned short g_code[(size_t)N_PAIRS * K_ELEMS];

// ---------------------------------------------------------------------------
// Kernel 1: per-pair lane-replicated shared-memory histogram + total weight
// + lookup-code generation. One block (512 thr) per pair.
// Layout sh[bin*32 + lane]: atomic address bank == lane -> 1-phase ATOMS.
// g_hist/g_tw are zero on entry (zeroed by cdf_kernel after use).
// ---------------------------------------------------------------------------
extern __shared__ float sh_hist[];   // NUM_BINS * NREP floats = 64 KB

__global__ __launch_bounds__(512) void hist_kernel(
    const float* __restrict__ res, const float* __restrict__ wgt,
    const int* __restrict__ src, const int* __restrict__ dst)
{
    __shared__ float sh_wsum;

    const int p    = blockIdx.x;
    const int tid  = threadIdx.x;
    const int lane = tid & 31;

    // zero 16384 floats with 512 threads (float4 stores, conflict-free)
    float4* shz = (float4*)sh_hist;
    #pragma unroll
    for (int i = 0; i < (NUM_BINS * NREP / 4) / 512; i++)
        shz[tid + i * 512] = make_float4(0.f, 0.f, 0.f, 0.f);
    if (tid == 0) sh_wsum = 0.0f;
    __syncthreads();

    const float4* r4 = (const float4*)(res + (size_t)p * K_ELEMS);
    const float4* w4 = (const float4*)(wgt + (size_t)p * K_ELEMS);
    ushort4* c4 = (ushort4*)(g_code + (size_t)p * K_ELEMS);

    float wsum = 0.0f;
    const int n4 = K_ELEMS / 4;
    for (int i = tid; i < n4; i += 512) {
        float4 rv = __ldcs(&r4[i]);   // read-once: stream past L2
        float4 wv = __ldcs(&w4[i]);
        float rr[4] = {rv.x, rv.y, rv.z, rv.w};
        float ww[4] = {wv.x, wv.y, wv.z, wv.w};
        unsigned short cc[4];
        #pragma unroll
        for (int j = 0; j < 4; j++) {
            wsum += ww[j];
            // histogram bin: floor(r*512)   (*2^9 exact in fp32)
            int b = (int)floorf(rr[j] * 512.0f);
            if (b >= 0 && b < NUM_BINS)
                atomicAdd(&sh_hist[b * NREP + lane], ww[j]);   // bank == lane
            // lookup bin: floor(r*512 + 0.5); valid also requires w > 0
            int b2 = (int)floorf(rr[j] * 512.0f + 0.5f);
            bool valid = (b2 >= 0) && (b2 < NUM_BINS) && (ww[j] > 0.0f);
            cc[j] = valid ? (unsigned short)b2 : (unsigned short)0xFFFFu;
        }
        c4[i] = make_ushort4(cc[0], cc[1], cc[2], cc[3]);
    }

    // warp-reduce wsum, one smem atomic per warp
    #pragma unroll
    for (int o = 16; o > 0; o >>= 1)
        wsum += __shfl_down_sync(0xffffffffu, wsum, o);
    if (lane == 0) atomicAdd(&sh_wsum, wsum);
    __syncthreads();

    // reduce 32 copies -> 1 value per bin; 512 threads == 512 bins.
    // rotated copy index keeps every LDS step conflict-free.
    const int bin = tid;
    float h = 0.0f;
    #pragma unroll
    for (int step = 0; step < NREP; step++)
        h += sh_hist[bin * NREP + ((lane + step) & 31)];

    const int s = src[p];
    const int d = dst[p];
    atomicAdd(&g_hist[s * NUM_BINS + bin], h);
    atomicAdd(&g_hist[d * NUM_BINS + bin], h);
    if (tid == 0) {
        atomicAdd(&g_tw[s], sh_wsum);
        atomicAdd(&g_tw[d], sh_wsum);
    }
}

// ---------------------------------------------------------------------------
// Kernel 2: cdf[node,:] = cumsum(hist[node,:] / (tw[node] + 1e-10)),
// then reset g_hist / g_tw to zero for the next invocation.
// ---------------------------------------------------------------------------
__global__ __launch_bounds__(512) void cdf_kernel() {
    __shared__ float warp_sums[16];

    const int node = blockIdx.x;
    const int tid  = threadIdx.x;

    const float inv_tw = 1.0f / (g_tw[node] + 1e-10f);
    float h = g_hist[node * NUM_BINS + tid];
    g_hist[node * NUM_BINS + tid] = 0.0f;     // reset for next call
    float x = h * inv_tw;

    #pragma unroll
    for (int o = 1; o < 32; o <<= 1) {
        float y = __shfl_up_sync(0xffffffffu, x, o);
        if ((tid & 31) >= o) x += y;
    }
    if ((tid & 31) == 31) warp_sums[tid >> 5] = x;
    __syncthreads();

    if (tid == 0) g_tw[node] = 0.0f;          // all reads of g_tw done pre-sync

    if (tid < 16) {
        float s = warp_sums[tid];
        #pragma unroll
        for (int o = 1; o < 16; o <<= 1) {
            float y = __shfl_up_sync(0x0000ffffu, s, o);
            if (tid >= o) s += y;
        }
        warp_sums[tid] = s;
    }
    __syncthreads();

    float base = (tid >= 32) ? warp_sums[(tid >> 5) - 1] : 0.0f;
    g_cdf[node * NUM_BINS + tid] = x + base;
}

// ---------------------------------------------------------------------------
// Kernel 3: lookup via cached 2-byte codes. One block per pair; the pair's
// two cdf rows staged in smem. Reads 2B/elem, writes 8B/elem.
// Output layout: out[0 : N*K) = src_cdf, out[N*K : 2*N*K) = dst_cdf.
// ---------------------------------------------------------------------------
__global__ __launch_bounds__(512) void lookup_kernel(
    const int* __restrict__ src, const int* __restrict__ dst,
    float* __restrict__ out)
{
    __shared__ float sh_s[NUM_BINS];
    __shared__ float sh_d[NUM_BINS];

    const int p   = blockIdx.x;
    const int tid = threadIdx.x;
    const int s   = src[p];
    const int d   = dst[p];

    for (int i = tid; i < NUM_BINS; i += 512) {
        sh_s[i] = g_cdf[s * NUM_BINS + i];
        sh_d[i] = g_cdf[d * NUM_BINS + i];
    }
    __syncthreads();

    const ushort4* c4 = (const ushort4*)(g_code + (size_t)p * K_ELEMS);
    float4* o_s = (float4*)(out + (size_t)p * K_ELEMS);
    float4* o_d = (float4*)(out + (size_t)(N_PAIRS + p) * K_ELEMS);

    const int n4 = K_ELEMS / 4;
    for (int i = tid; i < n4; i += 512) {
        ushort4 cv = c4[i];
        unsigned short cc[4] = {cv.x, cv.y, cv.z, cv.w};
        float4 os, od;
        float* pos = (float*)&os;
        float* pod = (float*)&od;
        #pragma unroll
        for (int j = 0; j < 4; j++) {
            unsigned short c = cc[j];
            if (c < NUM_BINS) {
                pos[j] = sh_s[c];
                pod[j] = sh_d[c];
            } else {
                pos[j] = 2.0f;
                pod[j] = 2.0f;
            }
        }
        __stcs(&o_s[i], os);   // streaming store: don't thrash L2
        __stcs(&o_d[i], od);
    }
}

// ---------------------------------------------------------------------------
extern "C" void kernel_launch(void* const* d_in, const int* in_sizes, int n_in,
                              void* d_out, int out_size)
{
    const float* res = (const float*)d_in[0];
    const float* wgt = (const float*)d_in[1];
    const int*   src = (const int*)d_in[2];
    const int*   dst = (const int*)d_in[3];
    float*       out = (float*)d_out;

    const int smem = NUM_BINS * NREP * sizeof(float);   // 64 KB
    cudaFuncSetAttribute(hist_kernel,
                         cudaFuncAttributeMaxDynamicSharedMemorySize, smem);

    hist_kernel<<<N_PAIRS, 512, smem>>>(res, wgt, src, dst);
    cdf_kernel<<<NUM_NODES, 512>>>();
    lookup_kernel<<<N_PAIRS, 512>>>(src, dst, out);
}

// round 4
// speedup vs baseline: 1.3459x; 1.0359x over previous
#include <cuda_runtime.h>

#define NUM_BINS  512
#define NUM_NODES 128
#define N_PAIRS   1024
#define K_ELEMS   16384
#define NREP      32   // one histogram copy per lane -> conflict-free ATOMS

// Scratch (allocation-free rule: __device__ globals, zero-initialized at load)
__device__ float g_hist[NUM_NODES * NUM_BINS];
__device__ float g_tw[NUM_NODES];
__device__ float g_cdf[NUM_NODES * NUM_BINS];
// 2-byte lookup code per element: bin index if valid, 0xFFFF sentinel if not.
__device__ unsigned short g_code[(size_t)N_PAIRS * K_ELEMS];

// ---------------------------------------------------------------------------
// Kernel 1: per-pair lane-replicated smem histogram + total weight + lookup
// codes. One block (512 thr) per pair; 8 chunks/thread, software-pipelined
// (prefetch depth 1) so 4 x 16B loads are always in flight per thread.
// ---------------------------------------------------------------------------
extern __shared__ float sh_hist[];   // NUM_BINS * NREP floats = 64 KB

__device__ __forceinline__ void hist_process(
    float4 rv, float4 wv, int lane, float& wsum, unsigned short* cc)
{
    float rr[4] = {rv.x, rv.y, rv.z, rv.w};
    float ww[4] = {wv.x, wv.y, wv.z, wv.w};
    #pragma unroll
    for (int j = 0; j < 4; j++) {
        wsum += ww[j];
        // histogram bin: floor(r*512)   (*2^9 exact in fp32)
        int b = (int)floorf(rr[j] * 512.0f);
        if (b >= 0 && b < NUM_BINS)
            atomicAdd(&sh_hist[b * NREP + lane], ww[j]);    // bank == lane
        // lookup bin: floor(r*512 + 0.5); valid also requires w > 0
        int b2 = (int)floorf(rr[j] * 512.0f + 0.5f);
        bool valid = (b2 >= 0) && (b2 < NUM_BINS) && (ww[j] > 0.0f);
        cc[j] = valid ? (unsigned short)b2 : (unsigned short)0xFFFFu;
    }
}

__global__ __launch_bounds__(512) void hist_kernel(
    const float* __restrict__ res, const float* __restrict__ wgt,
    const int* __restrict__ src, const int* __restrict__ dst)
{
    __shared__ float sh_wsum;

    const int p    = blockIdx.x;
    const int tid  = threadIdx.x;
    const int lane = tid & 31;

    // zero 16384 floats with 512 threads (float4 stores, conflict-free)
    float4* shz = (float4*)sh_hist;
    #pragma unroll
    for (int i = 0; i < (NUM_BINS * NREP / 4) / 512; i++)
        shz[tid + i * 512] = make_float4(0.f, 0.f, 0.f, 0.f);
    if (tid == 0) sh_wsum = 0.0f;
    __syncthreads();

    const float4* r4 = (const float4*)(res + (size_t)p * K_ELEMS);
    const float4* w4 = (const float4*)(wgt + (size_t)p * K_ELEMS);
    ushort4* c4 = (ushort4*)(g_code + (size_t)p * K_ELEMS);

    const int NIT = (K_ELEMS / 4) / 512;   // 8 chunks per thread

    // software pipeline: prefetch next chunk while processing current
    float4 rv = __ldcs(&r4[tid]);
    float4 wv = __ldcs(&w4[tid]);

    float wsum = 0.0f;
    #pragma unroll
    for (int it = 0; it < NIT; it++) {
        float4 rn, wn;
        if (it + 1 < NIT) {
            rn = __ldcs(&r4[tid + (it + 1) * 512]);
            wn = __ldcs(&w4[tid + (it + 1) * 512]);
        }
        unsigned short cc[4];
        hist_process(rv, wv, lane, wsum, cc);
        c4[tid + it * 512] = make_ushort4(cc[0], cc[1], cc[2], cc[3]);
        rv = rn;
        wv = wn;
    }

    // warp-reduce wsum, one smem atomic per warp
    #pragma unroll
    for (int o = 16; o > 0; o >>= 1)
        wsum += __shfl_down_sync(0xffffffffu, wsum, o);
    if (lane == 0) atomicAdd(&sh_wsum, wsum);
    __syncthreads();

    // reduce 32 copies -> 1 value per bin; 512 threads == 512 bins.
    // rotated copy index keeps every LDS step conflict-free.
    const int bin = tid;
    float h = 0.0f;
    #pragma unroll
    for (int step = 0; step < NREP; step++)
        h += sh_hist[bin * NREP + ((lane + step) & 31)];

    const int s = src[p];
    const int d = dst[p];
    atomicAdd(&g_hist[s * NUM_BINS + bin], h);
    atomicAdd(&g_hist[d * NUM_BINS + bin], h);
    if (tid == 0) {
        atomicAdd(&g_tw[s], sh_wsum);
        atomicAdd(&g_tw[d], sh_wsum);
    }
}

// ---------------------------------------------------------------------------
// Kernel 2: cdf[node,:] = cumsum(hist[node,:] / (tw[node] + 1e-10)),
// then reset g_hist / g_tw to zero for the next invocation.
// ---------------------------------------------------------------------------
__global__ __launch_bounds__(512) void cdf_kernel() {
    __shared__ float warp_sums[16];

    const int node = blockIdx.x;
    const int tid  = threadIdx.x;

    const float inv_tw = 1.0f / (g_tw[node] + 1e-10f);
    float h = g_hist[node * NUM_BINS + tid];
    g_hist[node * NUM_BINS + tid] = 0.0f;     // reset for next call
    float x = h * inv_tw;

    #pragma unroll
    for (int o = 1; o < 32; o <<= 1) {
        float y = __shfl_up_sync(0xffffffffu, x, o);
        if ((tid & 31) >= o) x += y;
    }
    if ((tid & 31) == 31) warp_sums[tid >> 5] = x;
    __syncthreads();

    if (tid == 0) g_tw[node] = 0.0f;          // all reads of g_tw done pre-sync

    if (tid < 16) {
        float s = warp_sums[tid];
        #pragma unroll
        for (int o = 1; o < 16; o <<= 1) {
            float y = __shfl_up_sync(0x0000ffffu, s, o);
            if (tid >= o) s += y;
        }
        warp_sums[tid] = s;
    }
    __syncthreads();

    float base = (tid >= 32) ? warp_sums[(tid >> 5) - 1] : 0.0f;
    g_cdf[node * NUM_BINS + tid] = x + base;
}

// ---------------------------------------------------------------------------
// Kernel 3: lookup via cached 2-byte codes, software-pipelined.
// One block per pair; the pair's two cdf rows staged in smem.
// Output layout: out[0 : N*K) = src_cdf, out[N*K : 2*N*K) = dst_cdf.
// ---------------------------------------------------------------------------
__device__ __forceinline__ void lookup_process(
    ushort4 cv, const float* sh_s, const float* sh_d, float4& os, float4& od)
{
    unsigned short cc[4] = {cv.x, cv.y, cv.z, cv.w};
    float* pos = (float*)&os;
    float* pod = (float*)&od;
    #pragma unroll
    for (int j = 0; j < 4; j++) {
        unsigned short c = cc[j];
        if (c < NUM_BINS) {
            pos[j] = sh_s[c];
            pod[j] = sh_d[c];
        } else {
            pos[j] = 2.0f;
            pod[j] = 2.0f;
        }
    }
}

__global__ __launch_bounds__(512) void lookup_kernel(
    const int* __restrict__ src, const int* __restrict__ dst,
    float* __restrict__ out)
{
    __shared__ float sh_s[NUM_BINS];
    __shared__ float sh_d[NUM_BINS];

    const int p   = blockIdx.x;
    const int tid = threadIdx.x;
    const int s   = src[p];
    const int d   = dst[p];

    for (int i = tid; i < NUM_BINS; i += 512) {
        sh_s[i] = g_cdf[s * NUM_BINS + i];
        sh_d[i] = g_cdf[d * NUM_BINS + i];
    }
    __syncthreads();

    const ushort4* c4 = (const ushort4*)(g_code + (size_t)p * K_ELEMS);
    float4* o_s = (float4*)(out + (size_t)p * K_ELEMS);
    float4* o_d = (float4*)(out + (size_t)(N_PAIRS + p) * K_ELEMS);

    const int NIT = (K_ELEMS / 4) / 512;   // 8 chunks per thread

    ushort4 cv = c4[tid];
    #pragma unroll
    for (int it = 0; it < NIT; it++) {
        ushort4 cn;
        if (it + 1 < NIT) cn = c4[tid + (it + 1) * 512];
        float4 os, od;
        lookup_process(cv, sh_s, sh_d, os, od);
        __stcs(&o_s[tid + it * 512], os);   // streaming: never re-read
        __stcs(&o_d[tid + it * 512], od);
        cv = cn;
    }
}

// ---------------------------------------------------------------------------
extern "C" void kernel_launch(void* const* d_in, const int* in_sizes, int n_in,
                              void* d_out, int out_size)
{
    const float* res = (const float*)d_in[0];
    const float* wgt = (const float*)d_in[1];
    const int*   src = (const int*)d_in[2];
    const int*   dst = (const int*)d_in[3];
    float*       out = (float*)d_out;

    const int smem = NUM_BINS * NREP * sizeof(float);   // 64 KB
    cudaFuncSetAttribute(hist_kernel,
                         cudaFuncAttributeMaxDynamicSharedMemorySize, smem);

    hist_kernel<<<N_PAIRS, 512, smem>>>(res, wgt, src, dst);
    cdf_kernel<<<NUM_NODES, 512>>>();
    lookup_kernel<<<N_PAIRS, 512>>>(src, dst, out);
}